// round 1
// baseline (speedup 1.0000x reference)
#include <cuda_runtime.h>
#include <cuda_bf16.h>

// SPA payment: for each row of x[N,16], out[j] = max( (j==argmax ? max2 : max1), 0 )
// One thread per row: 4x LDG.128 + 4x STG.128, fully coalesced.

__global__ __launch_bounds__(256)
void spa_payment_kernel(const float4* __restrict__ x,
                        float4* __restrict__ out,
                        int nrows) {
    int row = blockIdx.x * blockDim.x + threadIdx.x;
    if (row >= nrows) return;

    const float4* p = x + (size_t)row * 4;
    float4 a = p[0];
    float4 b = p[1];
    float4 c = p[2];
    float4 d = p[3];

    float v[16] = {a.x, a.y, a.z, a.w,
                   b.x, b.y, b.z, b.w,
                   c.x, c.y, c.z, c.w,
                   d.x, d.y, d.z, d.w};

    // top-2 with first-occurrence argmax (matches jax.lax.top_k tie rule)
    float m1 = v[0];
    float m2 = -__FLT_MAX__;
    int arg = 0;
#pragma unroll
    for (int j = 1; j < 16; j++) {
        float val = v[j];
        if (val > m1) {
            m2 = m1;
            m1 = val;
            arg = j;
        } else if (val > m2) {
            m2 = val;
        }
    }

    float o1 = fmaxf(m1, 0.0f);  // leave-one-out max for j != argmax
    float o2 = fmaxf(m2, 0.0f);  // leave-one-out max for j == argmax

    float o[16];
#pragma unroll
    for (int j = 0; j < 16; j++) {
        o[j] = (j == arg) ? o2 : o1;
    }

    float4* q = out + (size_t)row * 4;
    q[0] = make_float4(o[0],  o[1],  o[2],  o[3]);
    q[1] = make_float4(o[4],  o[5],  o[6],  o[7]);
    q[2] = make_float4(o[8],  o[9],  o[10], o[11]);
    q[3] = make_float4(o[12], o[13], o[14], o[15]);
}

extern "C" void kernel_launch(void* const* d_in, const int* in_sizes, int n_in,
                              void* d_out, int out_size) {
    const float* x = (const float*)d_in[0];
    float* out = (float*)d_out;
    int nrows = in_sizes[0] / 16;

    int block = 256;
    int grid = (nrows + block - 1) / block;
    spa_payment_kernel<<<grid, block>>>((const float4*)x, (float4*)out, nrows);
}

// round 2
// speedup vs baseline: 1.0678x; 1.0678x over previous
#include <cuda_runtime.h>
#include <cuda_bf16.h>

// SPA payment, coalesced variant: 4 threads per row of x[N,16].
// Each lane loads ONE float4 (warp request = 512B contiguous), local top-2,
// then butterfly-shuffle merge across the 4-lane group. Each lane writes one
// contiguous float4 of outputs. Streaming cache hints (no reuse).

__global__ __launch_bounds__(256)
void spa_payment_coalesced(const float4* __restrict__ x,
                           float4* __restrict__ out,
                           int nquads) {   // nquads = nrows * 4
    int qid = blockIdx.x * blockDim.x + threadIdx.x;
    // Rows occupy aligned groups of 4 quads, so either a whole 4-lane group is
    // in-bounds or the whole group is out; clamping keeps shuffles uniform.
    int qc = qid < nquads ? qid : (nquads - 1);

    float4 f = __ldcs(x + qc);

    // Local top-2 with first-occurrence argmax over this lane's 4 values.
    float v1 = f.y, v2 = f.z, v3 = f.w;
    float m1 = f.x, m2 = -__FLT_MAX__;
    int arg = 0;
    if (v1 > m1) { m2 = m1; m1 = v1; arg = 1; } else { m2 = v1; }
    if (v2 > m1) { m2 = m1; m1 = v2; arg = 2; } else if (v2 > m2) { m2 = v2; }
    if (v3 > m1) { m2 = m1; m1 = v3; arg = 3; } else if (v3 > m2) { m2 = v3; }

    // Globalize arg within the row (quarter index = qid & 3).
    int quarter = qid & 3;
    arg += quarter * 4;

    // Merge across the 4-lane group (lanes share row). Tie on m1 -> lower idx.
#pragma unroll
    for (int ofs = 1; ofs <= 2; ofs <<= 1) {
        float om1 = __shfl_xor_sync(0xffffffffu, m1, ofs);
        float om2 = __shfl_xor_sync(0xffffffffu, m2, ofs);
        int   oar = __shfl_xor_sync(0xffffffffu, arg, ofs);
        if (om1 > m1 || (om1 == m1 && oar < arg)) {
            m2 = fmaxf(m1, om2);
            m1 = om1;
            arg = oar;
        } else {
            m2 = fmaxf(om1, m2);
        }
    }

    float o1 = fmaxf(m1, 0.0f);   // leave-one-out max for j != argmax
    float o2 = fmaxf(m2, 0.0f);   // leave-one-out max for j == argmax

    int jb = quarter * 4;
    float4 o;
    o.x = (jb + 0 == arg) ? o2 : o1;
    o.y = (jb + 1 == arg) ? o2 : o1;
    o.z = (jb + 2 == arg) ? o2 : o1;
    o.w = (jb + 3 == arg) ? o2 : o1;

    if (qid < nquads) __stcs(out + qid, o);
}

extern "C" void kernel_launch(void* const* d_in, const int* in_sizes, int n_in,
                              void* d_out, int out_size) {
    const float* x = (const float*)d_in[0];
    float* out = (float*)d_out;
    int nquads = in_sizes[0] / 4;   // one float4 per thread

    int block = 256;
    int grid = (nquads + block - 1) / block;
    spa_payment_coalesced<<<grid, block>>>((const float4*)x, (float4*)out, nquads);
}

// round 3
// speedup vs baseline: 1.0999x; 1.0301x over previous
#include <cuda_runtime.h>
#include <cuda_bf16.h>

// SPA payment: 4 threads per row of x[N,16], TWO independent row-quarters per
// thread (batched loads -> MLP=2). Warp requests stay contiguous 512B.

__global__ __launch_bounds__(256)
void spa_payment_x2(const float4* __restrict__ x,
                    float4* __restrict__ out,
                    int nquads) {
    int q0 = blockIdx.x * (blockDim.x * 2) + threadIdx.x;
    int q1 = q0 + blockDim.x;

    // Exact-divisible in practice; clamp defensively (groups of 4 stay intact).
    int c0 = q0 < nquads ? q0 : (nquads - 1);
    int c1 = q1 < nquads ? q1 : (nquads - 1);

    // Front-batched loads (independent -> 2 outstanding LDG.128 per thread)
    float4 fa = __ldcs(x + c0);
    float4 fb = __ldcs(x + c1);

    int quarter = threadIdx.x & 3;   // same for q0 and q1 (offset 256 ≡ 0 mod 4)
    int jb = quarter * 4;

    // ---- local top-2 (first-occurrence argmax), reduction A ----
    float am1 = fa.x, am2 = -__FLT_MAX__; int aarg = jb;
    if (fa.y > am1) { am2 = am1; am1 = fa.y; aarg = jb + 1; } else { am2 = fa.y; }
    if (fa.z > am1) { am2 = am1; am1 = fa.z; aarg = jb + 2; } else if (fa.z > am2) { am2 = fa.z; }
    if (fa.w > am1) { am2 = am1; am1 = fa.w; aarg = jb + 3; } else if (fa.w > am2) { am2 = fa.w; }

    // ---- local top-2, reduction B ----
    float bm1 = fb.x, bm2 = -__FLT_MAX__; int barg = jb;
    if (fb.y > bm1) { bm2 = bm1; bm1 = fb.y; barg = jb + 1; } else { bm2 = fb.y; }
    if (fb.z > bm1) { bm2 = bm1; bm1 = fb.z; barg = jb + 2; } else if (fb.z > bm2) { bm2 = fb.z; }
    if (fb.w > bm1) { bm2 = bm1; bm1 = fb.w; barg = jb + 3; } else if (fb.w > bm2) { bm2 = fb.w; }

    // ---- interleaved 4-lane group merges (ties -> lower global index) ----
#pragma unroll
    for (int ofs = 1; ofs <= 2; ofs <<= 1) {
        float oam1 = __shfl_xor_sync(0xffffffffu, am1, ofs);
        float obm1 = __shfl_xor_sync(0xffffffffu, bm1, ofs);
        float oam2 = __shfl_xor_sync(0xffffffffu, am2, ofs);
        float obm2 = __shfl_xor_sync(0xffffffffu, bm2, ofs);
        int   oaar = __shfl_xor_sync(0xffffffffu, aarg, ofs);
        int   obar = __shfl_xor_sync(0xffffffffu, barg, ofs);

        if (oam1 > am1 || (oam1 == am1 && oaar < aarg)) {
            am2 = fmaxf(am1, oam2); am1 = oam1; aarg = oaar;
        } else {
            am2 = fmaxf(oam1, am2);
        }
        if (obm1 > bm1 || (obm1 == bm1 && obar < barg)) {
            bm2 = fmaxf(bm1, obm2); bm1 = obm1; barg = obar;
        } else {
            bm2 = fmaxf(obm1, bm2);
        }
    }

    float ao1 = fmaxf(am1, 0.0f), ao2 = fmaxf(am2, 0.0f);
    float bo1 = fmaxf(bm1, 0.0f), bo2 = fmaxf(bm2, 0.0f);

    float4 oa, ob;
    oa.x = (jb + 0 == aarg) ? ao2 : ao1;
    oa.y = (jb + 1 == aarg) ? ao2 : ao1;
    oa.z = (jb + 2 == aarg) ? ao2 : ao1;
    oa.w = (jb + 3 == aarg) ? ao2 : ao1;
    ob.x = (jb + 0 == barg) ? bo2 : bo1;
    ob.y = (jb + 1 == barg) ? bo2 : bo1;
    ob.z = (jb + 2 == barg) ? bo2 : bo1;
    ob.w = (jb + 3 == barg) ? bo2 : bo1;

    if (q0 < nquads) __stcs(out + q0, oa);
    if (q1 < nquads) __stcs(out + q1, ob);
}

extern "C" void kernel_launch(void* const* d_in, const int* in_sizes, int n_in,
                              void* d_out, int out_size) {
    const float* x = (const float*)d_in[0];
    float* out = (float*)d_out;
    int nquads = in_sizes[0] / 4;

    int block = 256;
    int per_block = block * 2;
    int grid = (nquads + per_block - 1) / per_block;
    spa_payment_x2<<<grid, block>>>((const float4*)x, (float4*)out, nquads);
}